// round 13
// baseline (speedup 1.0000x reference)
#include <cuda_runtime.h>
#include <cuda_bf16.h>
#include <cstdint>

// Problem constants (from reference setup_inputs)
#define BATCH  4096
#define CWDIM  1024
#define CODES  128     // C
#define BOOK   256     // K
#define DEMB   8       // D

#define THREADS 256
#define ROWS_PB 512    // 2 rows per thread

// ---- 256-bit global ld/st (sm_100+) ----
struct f8 { float v[8]; };

static __device__ __forceinline__ f8 ldg_v8(const float* p) {
    f8 r;
    asm volatile("ld.global.nc.v8.f32 {%0,%1,%2,%3,%4,%5,%6,%7}, [%8];"
                 : "=f"(r.v[0]), "=f"(r.v[1]), "=f"(r.v[2]), "=f"(r.v[3]),
                   "=f"(r.v[4]), "=f"(r.v[5]), "=f"(r.v[6]), "=f"(r.v[7])
                 : "l"(p));
    return r;
}

static __device__ __forceinline__ void stg_v8(float* p, const f8& r) {
    asm volatile("st.global.v8.f32 [%0], {%1,%2,%3,%4,%5,%6,%7,%8};"
                 :: "l"(p),
                    "f"(r.v[0]), "f"(r.v[1]), "f"(r.v[2]), "f"(r.v[3]),
                    "f"(r.v[4]), "f"(r.v[5]), "f"(r.v[6]), "f"(r.v[7])
                 : "memory");
}

// ---- packed fp32x2 (sm_103a native) ----
#define FMA2(acc, a, b) \
    asm("fma.rn.f32x2 %0, %1, %2, %0;" : "+l"(acc) : "l"(a), "l"(b))
#define UNPACK2(lo, hi, v) \
    asm("mov.b64 {%0, %1}, %2;" : "=f"(lo), "=f"(hi) : "l"(v))

static __device__ __forceinline__ unsigned long long pack2f(float a, float b) {
    unsigned long long r;
    asm("mov.b64 %0, {%1, %2};" : "=l"(r) : "f"(a), "f"(b));
    return r;
}

// ---------------------------------------------------------------------------
// Fused kernel: R11 argmin + lean two-store drain.
// grid = (BATCH/512, CODES) = (8,128), block = 256, one c per block.
// Drain: zero STG.256 per row-slot + same-thread predicated STG.32 of 1.0f.
// score(k) = 0.5*||c_k||^2 - x . c_k  (same argmin as full distance)
// ---------------------------------------------------------------------------
__global__ void __launch_bounds__(THREADS)
vq_fused_kernel(const float* __restrict__ x,
                const float* __restrict__ cb,
                float* __restrict__ cw_embed,
                float* __restrict__ one_hot)
{
    __shared__ float4             s_cb[BOOK * 2];          // 8 KB plain (gather)
    __shared__ unsigned long long s_pk[(BOOK / 2) * 8];    // 8 KB k-pair interleaved
    __shared__ unsigned long long s_hp[BOOK / 2];          // 1 KB (h_k0, h_k1)
    __shared__ unsigned char      s_idxT[ROWS_PB];         // [rsub][it] transposed

    const int c  = blockIdx.y;
    const int t  = threadIdx.x;
    const int b0 = blockIdx.x * ROWS_PB;

    // ---- Stage codebook[c]: thread t handles code k = t ----
    const float4* cb4 = reinterpret_cast<const float4*>(cb + (size_t)c * BOOK * DEMB);
    {
        float4 r0 = cb4[t * 2 + 0];
        float4 r1 = cb4[t * 2 + 1];
        s_cb[t * 2 + 0] = r0;
        s_cb[t * 2 + 1] = r1;
        float h = 0.5f * (r0.x * r0.x + r0.y * r0.y + r0.z * r0.z + r0.w * r0.w +
                          r1.x * r1.x + r1.y * r1.y + r1.z * r1.z + r1.w * r1.w);
        const int kp = t >> 1;
        const int ln = t & 1;
        unsigned* pk32 = reinterpret_cast<unsigned*>(s_pk);
        const float vals[8] = {r0.x, r0.y, r0.z, r0.w, r1.x, r1.y, r1.z, r1.w};
        #pragma unroll
        for (int d = 0; d < 8; ++d)
            pk32[(kp * 8 + d) * 2 + ln] = __float_as_uint(vals[d]);
        reinterpret_cast<unsigned*>(s_hp)[kp * 2 + ln] = __float_as_uint(h);
    }

    // ---- Load x for this thread's 2 rows; splat (-x_d, -x_d) once ----
    f8 xa = ldg_v8(x + (size_t)(b0 + t)       * CWDIM + c * DEMB);
    f8 xb = ldg_v8(x + (size_t)(b0 + 256 + t) * CWDIM + c * DEMB);
    unsigned long long xA[8], xB[8];
    #pragma unroll
    for (int d = 0; d < 8; ++d) {
        xA[d] = pack2f(-xa.v[d], -xa.v[d]);
        xB[d] = pack2f(-xb.v[d], -xb.v[d]);
    }

    __syncthreads();

    // ---- Argmin over 128 k-pairs for both rows (bit-exact vs R11) ----
    float bestA = 3.4e38f, bestB = 3.4e38f;
    int   biA = 0, biB = 0;

    const ulonglong2* pk2 = reinterpret_cast<const ulonglong2*>(s_pk);

    #pragma unroll 2
    for (int kp = 0; kp < BOOK / 2; ++kp) {
        const unsigned long long h = s_hp[kp];
        ulonglong2 q0 = pk2[kp * 4 + 0];
        ulonglong2 q1 = pk2[kp * 4 + 1];
        ulonglong2 q2 = pk2[kp * 4 + 2];
        ulonglong2 q3 = pk2[kp * 4 + 3];

        unsigned long long aA = h, aB = h;
        FMA2(aA, xA[0], q0.x);  FMA2(aB, xB[0], q0.x);
        FMA2(aA, xA[1], q0.y);  FMA2(aB, xB[1], q0.y);
        FMA2(aA, xA[2], q1.x);  FMA2(aB, xB[2], q1.x);
        FMA2(aA, xA[3], q1.y);  FMA2(aB, xB[3], q1.y);
        FMA2(aA, xA[4], q2.x);  FMA2(aB, xB[4], q2.x);
        FMA2(aA, xA[5], q2.y);  FMA2(aB, xB[5], q2.y);
        FMA2(aA, xA[6], q3.x);  FMA2(aB, xB[6], q3.x);
        FMA2(aA, xA[7], q3.y);  FMA2(aB, xB[7], q3.y);

        float sA0, sA1, sB0, sB1;
        UNPACK2(sA0, sA1, aA);
        UNPACK2(sB0, sB1, aB);

        const int k0 = kp * 2, k1 = kp * 2 + 1;
        // strict < in ascending-k order keeps FIRST minimum (jnp.argmin)
        if (sA0 < bestA) { bestA = sA0; biA = k0; }
        if (sA1 < bestA) { bestA = sA1; biA = k1; }
        if (sB0 < bestB) { bestB = sB0; biB = k0; }
        if (sB1 < bestB) { bestB = sB1; biB = k1; }
    }

    // ---- transposed index store: local row r -> s_idxT[(r&7)*64 + (r>>3)] ----
    // rowA local = t ; rowB local = t + 256 (same r&7, it offset +32)
    s_idxT[(t & 7) * 64 + (t >> 3)]      = (unsigned char)biA;
    s_idxT[(t & 7) * 64 + 32 + (t >> 3)] = (unsigned char)biB;

    // ---- cw_embed for both rows (one 32B store per row) ----
    {
        float4 pA0 = s_cb[2 * biA + 0], pA1 = s_cb[2 * biA + 1];
        f8 wa = { pA0.x, pA0.y, pA0.z, pA0.w, pA1.x, pA1.y, pA1.z, pA1.w };
        stg_v8(cw_embed + (size_t)(b0 + t) * CWDIM + c * DEMB, wa);

        float4 pB0 = s_cb[2 * biB + 0], pB1 = s_cb[2 * biB + 1];
        f8 wb = { pB0.x, pB0.y, pB0.z, pB0.w, pB1.x, pB1.y, pB1.z, pB1.w };
        stg_v8(cw_embed + (size_t)(b0 + 256 + t) * CWDIM + c * DEMB, wb);
    }

    __syncthreads();

    // ---- one_hot drain: 512 rows. Iteration it covers rows it*8 + rsub.
    // Per iteration: one zero STG.256 + (<=1 lane) predicated STG.32 of 1.0f.
    const int off  = t & 31;    // 8-float slot within row
    const int rsub = t >> 5;    // row within group of 8
    const unsigned kb = (unsigned)off * 8u;

    float* ohp = one_hot
               + (size_t)(b0 + rsub) * (CODES * BOOK)
               + (size_t)c * BOOK
               + (size_t)off * 8;
    const size_t step = (size_t)8 * (CODES * BOOK);   // 8 rows per iteration

    const f8 zero = { 0.f, 0.f, 0.f, 0.f, 0.f, 0.f, 0.f, 0.f };

    // indices for this thread: s_idxT[rsub*64 + it], it = 0..63 -> 8x LDS.64
    const unsigned long long* idx8 =
        reinterpret_cast<const unsigned long long*>(s_idxT) + rsub * 8;

    #pragma unroll
    for (int q = 0; q < 8; ++q) {
        unsigned long long pk = idx8[q];
        #pragma unroll
        for (int j = 0; j < 8; ++j) {
            const unsigned idx = (unsigned)(pk >> (8 * j)) & 0xFFu;
            stg_v8(ohp, zero);
            const unsigned d = idx - kb;          // in [0,8) iff this lane owns it
            if (d < 8u)
                ohp[d] = 1.0f;                    // same thread, after its zero
            ohp += step;
        }
    }
}

// ---------------------------------------------------------------------------
extern "C" void kernel_launch(void* const* d_in, const int* in_sizes, int n_in,
                              void* d_out, int out_size)
{
    const float* x  = (const float*)d_in[0];   // [4096, 1024]
    const float* cb = (const float*)d_in[1];   // [128, 256, 8]

    float* cw_embed = (float*)d_out;                               // [4096, 1024]
    float* one_hot  = (float*)d_out + (size_t)BATCH * CWDIM;       // [4096, 128, 256]

    dim3 grid(BATCH / ROWS_PB, CODES);                             // (8, 128)
    vq_fused_kernel<<<grid, THREADS>>>(x, cb, cw_embed, one_hot);
}

// round 14
// speedup vs baseline: 1.0506x; 1.0506x over previous
#include <cuda_runtime.h>
#include <cuda_bf16.h>
#include <cstdint>

// Problem constants (from reference setup_inputs)
#define BATCH  4096
#define CWDIM  1024
#define CODES  128     // C
#define BOOK   256     // K
#define DEMB   8       // D

#define THREADS 256
#define ROWS_PB 512    // 2 rows per thread

// ---- 256-bit global ld/st (sm_100+) ----
struct f8 { float v[8]; };

static __device__ __forceinline__ f8 ldg_v8(const float* p) {
    f8 r;
    asm volatile("ld.global.nc.v8.f32 {%0,%1,%2,%3,%4,%5,%6,%7}, [%8];"
                 : "=f"(r.v[0]), "=f"(r.v[1]), "=f"(r.v[2]), "=f"(r.v[3]),
                   "=f"(r.v[4]), "=f"(r.v[5]), "=f"(r.v[6]), "=f"(r.v[7])
                 : "l"(p));
    return r;
}

static __device__ __forceinline__ void stg_v8(float* p, const f8& r) {
    asm volatile("st.global.v8.f32 [%0], {%1,%2,%3,%4,%5,%6,%7,%8};"
                 :: "l"(p),
                    "f"(r.v[0]), "f"(r.v[1]), "f"(r.v[2]), "f"(r.v[3]),
                    "f"(r.v[4]), "f"(r.v[5]), "f"(r.v[6]), "f"(r.v[7])
                 : "memory");
}

// ---- packed fp32x2 (sm_103a native) ----
#define FMA2(acc, a, b) \
    asm("fma.rn.f32x2 %0, %1, %2, %0;" : "+l"(acc) : "l"(a), "l"(b))
#define UNPACK2(lo, hi, v) \
    asm("mov.b64 {%0, %1}, %2;" : "=f"(lo), "=f"(hi) : "l"(v))

static __device__ __forceinline__ unsigned long long pack2f(float a, float b) {
    unsigned long long r;
    asm("mov.b64 %0, {%1, %2};" : "=l"(r) : "f"(a), "f"(b));
    return r;
}

// ---------------------------------------------------------------------------
// Fused kernel: R11 argmin/drain + amortized smem index & h fetches.
// grid = (BATCH/512, CODES) = (8,128), block = 256, one c per block.
// Drain: ONE value STG.256 per line (single-visit; R13 lesson).
// score(k) = 0.5*||c_k||^2 - x . c_k  (same argmin as full distance)
// ---------------------------------------------------------------------------
__global__ void __launch_bounds__(THREADS)
vq_fused_kernel(const float* __restrict__ x,
                const float* __restrict__ cb,
                float* __restrict__ cw_embed,
                float* __restrict__ one_hot)
{
    __shared__ float4             s_cb[BOOK * 2];          // 8 KB plain (gather)
    __shared__ unsigned long long s_pk[(BOOK / 2) * 8];    // 8 KB k-pair interleaved
    __shared__ unsigned long long s_hp[BOOK / 2];          // 1 KB (h_k0, h_k1)
    __shared__ unsigned char      s_idxT[ROWS_PB];         // [rsub][it] transposed

    const int c  = blockIdx.y;
    const int t  = threadIdx.x;
    const int b0 = blockIdx.x * ROWS_PB;

    // ---- Stage codebook[c]: thread t handles code k = t ----
    const float4* cb4 = reinterpret_cast<const float4*>(cb + (size_t)c * BOOK * DEMB);
    {
        float4 r0 = cb4[t * 2 + 0];
        float4 r1 = cb4[t * 2 + 1];
        s_cb[t * 2 + 0] = r0;
        s_cb[t * 2 + 1] = r1;
        float h = 0.5f * (r0.x * r0.x + r0.y * r0.y + r0.z * r0.z + r0.w * r0.w +
                          r1.x * r1.x + r1.y * r1.y + r1.z * r1.z + r1.w * r1.w);
        const int kp = t >> 1;
        const int ln = t & 1;
        unsigned* pk32 = reinterpret_cast<unsigned*>(s_pk);
        const float vals[8] = {r0.x, r0.y, r0.z, r0.w, r1.x, r1.y, r1.z, r1.w};
        #pragma unroll
        for (int d = 0; d < 8; ++d)
            pk32[(kp * 8 + d) * 2 + ln] = __float_as_uint(vals[d]);
        reinterpret_cast<unsigned*>(s_hp)[kp * 2 + ln] = __float_as_uint(h);
    }

    // ---- Load x for this thread's 2 rows; splat (-x_d, -x_d) once ----
    f8 xa = ldg_v8(x + (size_t)(b0 + t)       * CWDIM + c * DEMB);
    f8 xb = ldg_v8(x + (size_t)(b0 + 256 + t) * CWDIM + c * DEMB);
    unsigned long long xA[8], xB[8];
    #pragma unroll
    for (int d = 0; d < 8; ++d) {
        xA[d] = pack2f(-xa.v[d], -xa.v[d]);
        xB[d] = pack2f(-xb.v[d], -xb.v[d]);
    }

    __syncthreads();

    // ---- Argmin over 128 k-pairs for both rows (bit-exact vs R11).
    // h fetched as ulonglong2 (one LDS.128 per 2 k-pairs).
    float bestA = 3.4e38f, bestB = 3.4e38f;
    int   biA = 0, biB = 0;

    const ulonglong2* pk2 = reinterpret_cast<const ulonglong2*>(s_pk);
    const ulonglong2* hp2 = reinterpret_cast<const ulonglong2*>(s_hp);

    #pragma unroll 2
    for (int kq = 0; kq < BOOK / 4; ++kq) {       // 2 k-pairs per iteration
        const ulonglong2 hh = hp2[kq];
        #pragma unroll
        for (int half = 0; half < 2; ++half) {
            const int kp = kq * 2 + half;
            const unsigned long long h = half ? hh.y : hh.x;
            ulonglong2 q0 = pk2[kp * 4 + 0];
            ulonglong2 q1 = pk2[kp * 4 + 1];
            ulonglong2 q2 = pk2[kp * 4 + 2];
            ulonglong2 q3 = pk2[kp * 4 + 3];

            unsigned long long aA = h, aB = h;
            FMA2(aA, xA[0], q0.x);  FMA2(aB, xB[0], q0.x);
            FMA2(aA, xA[1], q0.y);  FMA2(aB, xB[1], q0.y);
            FMA2(aA, xA[2], q1.x);  FMA2(aB, xB[2], q1.x);
            FMA2(aA, xA[3], q1.y);  FMA2(aB, xB[3], q1.y);
            FMA2(aA, xA[4], q2.x);  FMA2(aB, xB[4], q2.x);
            FMA2(aA, xA[5], q2.y);  FMA2(aB, xB[5], q2.y);
            FMA2(aA, xA[6], q3.x);  FMA2(aB, xB[6], q3.x);
            FMA2(aA, xA[7], q3.y);  FMA2(aB, xB[7], q3.y);

            float sA0, sA1, sB0, sB1;
            UNPACK2(sA0, sA1, aA);
            UNPACK2(sB0, sB1, aB);

            const int k0 = kp * 2, k1 = kp * 2 + 1;
            // strict < in ascending-k order keeps FIRST minimum (jnp.argmin)
            if (sA0 < bestA) { bestA = sA0; biA = k0; }
            if (sA1 < bestA) { bestA = sA1; biA = k1; }
            if (sB0 < bestB) { bestB = sB0; biB = k0; }
            if (sB1 < bestB) { bestB = sB1; biB = k1; }
        }
    }

    // ---- transposed index store: local row r -> s_idxT[(r&7)*64 + (r>>3)]
    // rowA local = t (r>>3 in 0..31); rowB local = t+256 (same r&7, it+32)
    s_idxT[(t & 7) * 64 + (t >> 3)]      = (unsigned char)biA;
    s_idxT[(t & 7) * 64 + 32 + (t >> 3)] = (unsigned char)biB;

    // ---- cw_embed for both rows (one 32B store per row) ----
    {
        float4 pA0 = s_cb[2 * biA + 0], pA1 = s_cb[2 * biA + 1];
        f8 wa = { pA0.x, pA0.y, pA0.z, pA0.w, pA1.x, pA1.y, pA1.z, pA1.w };
        stg_v8(cw_embed + (size_t)(b0 + t) * CWDIM + c * DEMB, wa);

        float4 pB0 = s_cb[2 * biB + 0], pB1 = s_cb[2 * biB + 1];
        f8 wb = { pB0.x, pB0.y, pB0.z, pB0.w, pB1.x, pB1.y, pB1.z, pB1.w };
        stg_v8(cw_embed + (size_t)(b0 + 256 + t) * CWDIM + c * DEMB, wb);
    }

    __syncthreads();

    // ---- one_hot drain (R11 values, single-visit stores): iteration it
    // covers rows it*8 + rsub; one value STG.256 per 32B line chunk.
    // Indices fetched 8-at-a-time via LDS.64 from the transposed array.
    const int off  = t & 31;    // 8-float slot within row
    const int rsub = t >> 5;    // row within group of 8
    const unsigned kb = (unsigned)off * 8u;

    float* ohp = one_hot
               + (size_t)(b0 + rsub) * (CODES * BOOK)
               + (size_t)c * BOOK
               + (size_t)off * 8;
    const size_t step = (size_t)8 * (CODES * BOOK);   // 8 rows per iteration

    const unsigned long long* idx8 =
        reinterpret_cast<const unsigned long long*>(s_idxT) + rsub * 8;

    #pragma unroll
    for (int q = 0; q < 8; ++q) {
        unsigned long long pk = idx8[q];
        #pragma unroll
        for (int j = 0; j < 8; ++j) {
            const unsigned idx = (unsigned)(pk >> (8 * j)) & 0xFFu;
            f8 v;
            #pragma unroll
            for (int e = 0; e < 8; ++e)
                v.v[e] = (idx == kb + (unsigned)e) ? 1.0f : 0.0f;
            stg_v8(ohp, v);
            ohp += step;
        }
    }
}

// ---------------------------------------------------------------------------
extern "C" void kernel_launch(void* const* d_in, const int* in_sizes, int n_in,
                              void* d_out, int out_size)
{
    const float* x  = (const float*)d_in[0];   // [4096, 1024]
    const float* cb = (const float*)d_in[1];   // [128, 256, 8]

    float* cw_embed = (float*)d_out;                               // [4096, 1024]
    float* one_hot  = (float*)d_out + (size_t)BATCH * CWDIM;       // [4096, 128, 256]

    dim3 grid(BATCH / ROWS_PB, CODES);                             // (8, 128)
    vq_fused_kernel<<<grid, THREADS>>>(x, cb, cw_embed, one_hot);
}

// round 15
// speedup vs baseline: 1.1731x; 1.1166x over previous
#include <cuda_runtime.h>
#include <cuda_bf16.h>
#include <cstdint>

// Problem constants (from reference setup_inputs)
#define BATCH  4096
#define CWDIM  1024
#define CODES  128     // C
#define BOOK   256     // K
#define DEMB   8       // D

#define THREADS 256
#define ROWS_PB 512    // 2 rows per thread

// ---- 256-bit global ld/st (sm_100+) ----
struct f8 { float v[8]; };

static __device__ __forceinline__ f8 ldg_v8(const float* p) {
    f8 r;
    asm volatile("ld.global.nc.v8.f32 {%0,%1,%2,%3,%4,%5,%6,%7}, [%8];"
                 : "=f"(r.v[0]), "=f"(r.v[1]), "=f"(r.v[2]), "=f"(r.v[3]),
                   "=f"(r.v[4]), "=f"(r.v[5]), "=f"(r.v[6]), "=f"(r.v[7])
                 : "l"(p));
    return r;
}

static __device__ __forceinline__ void stg_v8(float* p, const f8& r) {
    asm volatile("st.global.v8.f32 [%0], {%1,%2,%3,%4,%5,%6,%7,%8};"
                 :: "l"(p),
                    "f"(r.v[0]), "f"(r.v[1]), "f"(r.v[2]), "f"(r.v[3]),
                    "f"(r.v[4]), "f"(r.v[5]), "f"(r.v[6]), "f"(r.v[7])
                 : "memory");
}

// ---- packed fp32x2 (sm_103a native) ----
#define FMA2(acc, a, b) \
    asm("fma.rn.f32x2 %0, %1, %2, %0;" : "+l"(acc) : "l"(a), "l"(b))
#define UNPACK2(lo, hi, v) \
    asm("mov.b64 {%0, %1}, %2;" : "=f"(lo), "=f"(hi) : "l"(v))

static __device__ __forceinline__ unsigned long long pack2f(float a, float b) {
    unsigned long long r;
    asm("mov.b64 %0, {%1, %2};" : "=l"(r) : "f"(a), "f"(b));
    return r;
}

// ---------------------------------------------------------------------------
// Fused kernel (R11 verbatim; grid axes swapped for write locality).
// grid = (CODES, BATCH/512) = (128,8), block = 256, one c per block.
//   c = blockIdx.x   (varies fastest across consecutive block ids)
//   batch group = blockIdx.y
// Consecutive blocks cover contiguous output slabs -> dense DRAM pages.
// score(k) = 0.5*||c_k||^2 - x . c_k  (same argmin as full distance)
// ---------------------------------------------------------------------------
__global__ void __launch_bounds__(THREADS)
vq_fused_kernel(const float* __restrict__ x,
                const float* __restrict__ cb,
                float* __restrict__ cw_embed,
                float* __restrict__ one_hot)
{
    __shared__ float4             s_cb[BOOK * 2];          // 8 KB plain (gather)
    __shared__ unsigned long long s_pk[(BOOK / 2) * 8];    // 8 KB k-pair interleaved
    __shared__ unsigned long long s_hp[BOOK / 2];          // 1 KB (h_k0, h_k1)
    __shared__ unsigned char      s_idx[ROWS_PB];

    const int c  = blockIdx.x;                 // swapped
    const int t  = threadIdx.x;
    const int b0 = blockIdx.y * ROWS_PB;       // swapped

    // ---- Stage codebook[c]: thread t handles code k = t ----
    const float4* cb4 = reinterpret_cast<const float4*>(cb + (size_t)c * BOOK * DEMB);
    {
        float4 r0 = cb4[t * 2 + 0];
        float4 r1 = cb4[t * 2 + 1];
        s_cb[t * 2 + 0] = r0;
        s_cb[t * 2 + 1] = r1;
        float h = 0.5f * (r0.x * r0.x + r0.y * r0.y + r0.z * r0.z + r0.w * r0.w +
                          r1.x * r1.x + r1.y * r1.y + r1.z * r1.z + r1.w * r1.w);
        const int kp = t >> 1;
        const int ln = t & 1;
        unsigned* pk32 = reinterpret_cast<unsigned*>(s_pk);
        const float vals[8] = {r0.x, r0.y, r0.z, r0.w, r1.x, r1.y, r1.z, r1.w};
        #pragma unroll
        for (int d = 0; d < 8; ++d)
            pk32[(kp * 8 + d) * 2 + ln] = __float_as_uint(vals[d]);
        reinterpret_cast<unsigned*>(s_hp)[kp * 2 + ln] = __float_as_uint(h);
    }

    // ---- Load x for this thread's 2 rows; splat (-x_d, -x_d) once ----
    f8 xa = ldg_v8(x + (size_t)(b0 + t)       * CWDIM + c * DEMB);
    f8 xb = ldg_v8(x + (size_t)(b0 + 256 + t) * CWDIM + c * DEMB);
    unsigned long long xA[8], xB[8];
    #pragma unroll
    for (int d = 0; d < 8; ++d) {
        xA[d] = pack2f(-xa.v[d], -xa.v[d]);
        xB[d] = pack2f(-xb.v[d], -xb.v[d]);
    }

    __syncthreads();

    // ---- Argmin over 128 k-pairs for both rows ----
    float bestA = 3.4e38f, bestB = 3.4e38f;
    int   biA = 0, biB = 0;

    const ulonglong2* pk2 = reinterpret_cast<const ulonglong2*>(s_pk);

    #pragma unroll 2
    for (int kp = 0; kp < BOOK / 2; ++kp) {
        const unsigned long long h = s_hp[kp];
        ulonglong2 q0 = pk2[kp * 4 + 0];
        ulonglong2 q1 = pk2[kp * 4 + 1];
        ulonglong2 q2 = pk2[kp * 4 + 2];
        ulonglong2 q3 = pk2[kp * 4 + 3];

        unsigned long long aA = h, aB = h;
        FMA2(aA, xA[0], q0.x);  FMA2(aB, xB[0], q0.x);
        FMA2(aA, xA[1], q0.y);  FMA2(aB, xB[1], q0.y);
        FMA2(aA, xA[2], q1.x);  FMA2(aB, xB[2], q1.x);
        FMA2(aA, xA[3], q1.y);  FMA2(aB, xB[3], q1.y);
        FMA2(aA, xA[4], q2.x);  FMA2(aB, xB[4], q2.x);
        FMA2(aA, xA[5], q2.y);  FMA2(aB, xB[5], q2.y);
        FMA2(aA, xA[6], q3.x);  FMA2(aB, xB[6], q3.x);
        FMA2(aA, xA[7], q3.y);  FMA2(aB, xB[7], q3.y);

        float sA0, sA1, sB0, sB1;
        UNPACK2(sA0, sA1, aA);
        UNPACK2(sB0, sB1, aB);

        const int k0 = kp * 2, k1 = kp * 2 + 1;
        // strict < in ascending-k order keeps FIRST minimum (jnp.argmin)
        if (sA0 < bestA) { bestA = sA0; biA = k0; }
        if (sA1 < bestA) { bestA = sA1; biA = k1; }
        if (sB0 < bestB) { bestB = sB0; biB = k0; }
        if (sB1 < bestB) { bestB = sB1; biB = k1; }
    }

    s_idx[t]       = (unsigned char)biA;
    s_idx[t + 256] = (unsigned char)biB;

    // ---- cw_embed for both rows (one 32B store per row) ----
    {
        float4 pA0 = s_cb[2 * biA + 0], pA1 = s_cb[2 * biA + 1];
        f8 wa = { pA0.x, pA0.y, pA0.z, pA0.w, pA1.x, pA1.y, pA1.z, pA1.w };
        stg_v8(cw_embed + (size_t)(b0 + t) * CWDIM + c * DEMB, wa);

        float4 pB0 = s_cb[2 * biB + 0], pB1 = s_cb[2 * biB + 1];
        f8 wb = { pB0.x, pB0.y, pB0.z, pB0.w, pB1.x, pB1.y, pB1.z, pB1.w };
        stg_v8(cw_embed + (size_t)(b0 + 256 + t) * CWDIM + c * DEMB, wb);
    }

    __syncthreads();

    // ---- one_hot drain: 512 rows x 256 floats, STG.256.
    // 32 threads cover one 1KB row per warp-instruction; 8 rows per iter.
    const int off  = t & 31;    // 8-float slot within row
    const int rsub = t >> 5;    // row within group of 8
    const unsigned kb = (unsigned)off * 8u;

    float* ohp = one_hot
               + (size_t)(b0 + rsub) * (CODES * BOOK)
               + (size_t)c * BOOK
               + (size_t)off * 8;
    const size_t step = (size_t)8 * (CODES * BOOK);

    #pragma unroll 4
    for (int it = 0; it < ROWS_PB / 8; ++it) {
        const unsigned idx = s_idx[it * 8 + rsub];
        f8 v;
        #pragma unroll
        for (int j = 0; j < 8; ++j)
            v.v[j] = (idx == kb + (unsigned)j) ? 1.0f : 0.0f;
        stg_v8(ohp, v);
        ohp += step;
    }
}

// ---------------------------------------------------------------------------
extern "C" void kernel_launch(void* const* d_in, const int* in_sizes, int n_in,
                              void* d_out, int out_size)
{
    const float* x  = (const float*)d_in[0];   // [4096, 1024]
    const float* cb = (const float*)d_in[1];   // [128, 256, 8]

    float* cw_embed = (float*)d_out;                               // [4096, 1024]
    float* one_hot  = (float*)d_out + (size_t)BATCH * CWDIM;       // [4096, 128, 256]

    dim3 grid(CODES, BATCH / ROWS_PB);                             // (128, 8) swapped
    vq_fused_kernel<<<grid, THREADS>>>(x, cb, cw_embed, one_hot);
}

// round 16
// speedup vs baseline: 1.2202x; 1.0401x over previous
#include <cuda_runtime.h>
#include <cuda_bf16.h>
#include <cstdint>

// Problem constants (from reference setup_inputs)
#define BATCH  4096
#define CWDIM  1024
#define CODES  128     // C
#define BOOK   256     // K
#define DEMB   8       // D

#define THREADS 256
#define ROWS_PB 512    // 2 rows per thread

// ---- 256-bit global ld/st (sm_100+) ----
struct f8 { float v[8]; };

static __device__ __forceinline__ f8 ldg_v8(const float* p) {
    f8 r;
    asm volatile("ld.global.nc.v8.f32 {%0,%1,%2,%3,%4,%5,%6,%7}, [%8];"
                 : "=f"(r.v[0]), "=f"(r.v[1]), "=f"(r.v[2]), "=f"(r.v[3]),
                   "=f"(r.v[4]), "=f"(r.v[5]), "=f"(r.v[6]), "=f"(r.v[7])
                 : "l"(p));
    return r;
}

static __device__ __forceinline__ void stg_v8(float* p, const f8& r) {
    asm volatile("st.global.v8.f32 [%0], {%1,%2,%3,%4,%5,%6,%7,%8};"
                 :: "l"(p),
                    "f"(r.v[0]), "f"(r.v[1]), "f"(r.v[2]), "f"(r.v[3]),
                    "f"(r.v[4]), "f"(r.v[5]), "f"(r.v[6]), "f"(r.v[7])
                 : "memory");
}

// ---- packed fp32x2 (sm_103a native) ----
#define FMA2(acc, a, b) \
    asm("fma.rn.f32x2 %0, %1, %2, %0;" : "+l"(acc) : "l"(a), "l"(b))
#define UNPACK2(lo, hi, v) \
    asm("mov.b64 {%0, %1}, %2;" : "=f"(lo), "=f"(hi) : "l"(v))

static __device__ __forceinline__ unsigned long long pack2f(float a, float b) {
    unsigned long long r;
    asm("mov.b64 %0, {%1, %2};" : "=l"(r) : "f"(a), "f"(b));
    return r;
}

// ---------------------------------------------------------------------------
// Fused kernel (R11, the converged optimum):
// grid = (BATCH/512, CODES) = (8,128), block = 256, one c per block.
// Codebook stored k-pair interleaved: s_pk[kp*8+d] = (cb[2kp][d], cb[2kp+1][d]).
// Accumulator lane pair = scores of codes (2kp, 2kp+1) for one row.
// Drain: one value STG.256 per 32B output chunk (single-visit stores).
// score(k) = 0.5*||c_k||^2 - x . c_k  (same argmin as full distance)
// ---------------------------------------------------------------------------
__global__ void __launch_bounds__(THREADS)
vq_fused_kernel(const float* __restrict__ x,
                const float* __restrict__ cb,
                float* __restrict__ cw_embed,
                float* __restrict__ one_hot)
{
    __shared__ float4             s_cb[BOOK * 2];          // 8 KB plain (gather)
    __shared__ unsigned long long s_pk[(BOOK / 2) * 8];    // 8 KB k-pair interleaved
    __shared__ unsigned long long s_hp[BOOK / 2];          // 1 KB (h_k0, h_k1)
    __shared__ unsigned char      s_idx[ROWS_PB];

    const int c  = blockIdx.y;
    const int t  = threadIdx.x;
    const int b0 = blockIdx.x * ROWS_PB;

    // ---- Stage codebook[c]: thread t handles code k = t ----
    const float4* cb4 = reinterpret_cast<const float4*>(cb + (size_t)c * BOOK * DEMB);
    {
        float4 r0 = cb4[t * 2 + 0];
        float4 r1 = cb4[t * 2 + 1];
        s_cb[t * 2 + 0] = r0;
        s_cb[t * 2 + 1] = r1;
        float h = 0.5f * (r0.x * r0.x + r0.y * r0.y + r0.z * r0.z + r0.w * r0.w +
                          r1.x * r1.x + r1.y * r1.y + r1.z * r1.z + r1.w * r1.w);
        const int kp = t >> 1;
        const int ln = t & 1;
        unsigned* pk32 = reinterpret_cast<unsigned*>(s_pk);
        const float vals[8] = {r0.x, r0.y, r0.z, r0.w, r1.x, r1.y, r1.z, r1.w};
        #pragma unroll
        for (int d = 0; d < 8; ++d)
            pk32[(kp * 8 + d) * 2 + ln] = __float_as_uint(vals[d]);
        reinterpret_cast<unsigned*>(s_hp)[kp * 2 + ln] = __float_as_uint(h);
    }

    // ---- Load x for this thread's 2 rows; splat (-x_d, -x_d) once ----
    f8 xa = ldg_v8(x + (size_t)(b0 + t)       * CWDIM + c * DEMB);
    f8 xb = ldg_v8(x + (size_t)(b0 + 256 + t) * CWDIM + c * DEMB);
    unsigned long long xA[8], xB[8];
    #pragma unroll
    for (int d = 0; d < 8; ++d) {
        xA[d] = pack2f(-xa.v[d], -xa.v[d]);
        xB[d] = pack2f(-xb.v[d], -xb.v[d]);
    }

    __syncthreads();

    // ---- Argmin over 128 k-pairs for both rows ----
    float bestA = 3.4e38f, bestB = 3.4e38f;
    int   biA = 0, biB = 0;

    const ulonglong2* pk2 = reinterpret_cast<const ulonglong2*>(s_pk);

    #pragma unroll 2
    for (int kp = 0; kp < BOOK / 2; ++kp) {
        const unsigned long long h = s_hp[kp];
        ulonglong2 q0 = pk2[kp * 4 + 0];
        ulonglong2 q1 = pk2[kp * 4 + 1];
        ulonglong2 q2 = pk2[kp * 4 + 2];
        ulonglong2 q3 = pk2[kp * 4 + 3];

        unsigned long long aA = h, aB = h;
        FMA2(aA, xA[0], q0.x);  FMA2(aB, xB[0], q0.x);
        FMA2(aA, xA[1], q0.y);  FMA2(aB, xB[1], q0.y);
        FMA2(aA, xA[2], q1.x);  FMA2(aB, xB[2], q1.x);
        FMA2(aA, xA[3], q1.y);  FMA2(aB, xB[3], q1.y);
        FMA2(aA, xA[4], q2.x);  FMA2(aB, xB[4], q2.x);
        FMA2(aA, xA[5], q2.y);  FMA2(aB, xB[5], q2.y);
        FMA2(aA, xA[6], q3.x);  FMA2(aB, xB[6], q3.x);
        FMA2(aA, xA[7], q3.y);  FMA2(aB, xB[7], q3.y);

        float sA0, sA1, sB0, sB1;
        UNPACK2(sA0, sA1, aA);
        UNPACK2(sB0, sB1, aB);

        const int k0 = kp * 2, k1 = kp * 2 + 1;
        // strict < in ascending-k order keeps FIRST minimum (jnp.argmin)
        if (sA0 < bestA) { bestA = sA0; biA = k0; }
        if (sA1 < bestA) { bestA = sA1; biA = k1; }
        if (sB0 < bestB) { bestB = sB0; biB = k0; }
        if (sB1 < bestB) { bestB = sB1; biB = k1; }
    }

    s_idx[t]       = (unsigned char)biA;
    s_idx[t + 256] = (unsigned char)biB;

    // ---- cw_embed for both rows (one 32B store per row) ----
    {
        float4 pA0 = s_cb[2 * biA + 0], pA1 = s_cb[2 * biA + 1];
        f8 wa = { pA0.x, pA0.y, pA0.z, pA0.w, pA1.x, pA1.y, pA1.z, pA1.w };
        stg_v8(cw_embed + (size_t)(b0 + t) * CWDIM + c * DEMB, wa);

        float4 pB0 = s_cb[2 * biB + 0], pB1 = s_cb[2 * biB + 1];
        f8 wb = { pB0.x, pB0.y, pB0.z, pB0.w, pB1.x, pB1.y, pB1.z, pB1.w };
        stg_v8(cw_embed + (size_t)(b0 + 256 + t) * CWDIM + c * DEMB, wb);
    }

    __syncthreads();

    // ---- one_hot drain: 512 rows x 256 floats, STG.256.
    // 32 threads cover one 1KB row per warp-instruction; 8 rows per iter.
    const int off  = t & 31;    // 8-float slot within row
    const int rsub = t >> 5;    // row within group of 8
    const unsigned kb = (unsigned)off * 8u;

    float* ohp = one_hot
               + (size_t)(b0 + rsub) * (CODES * BOOK)
               + (size_t)c * BOOK
               + (size_t)off * 8;
    const size_t step = (size_t)8 * (CODES * BOOK);

    #pragma unroll 4
    for (int it = 0; it < ROWS_PB / 8; ++it) {
        const unsigned idx = s_idx[it * 8 + rsub];
        f8 v;
        #pragma unroll
        for (int j = 0; j < 8; ++j)
            v.v[j] = (idx == kb + (unsigned)j) ? 1.0f : 0.0f;
        stg_v8(ohp, v);
        ohp += step;
    }
}

// ---------------------------------------------------------------------------
extern "C" void kernel_launch(void* const* d_in, const int* in_sizes, int n_in,
                              void* d_out, int out_size)
{
    const float* x  = (const float*)d_in[0];   // [4096, 1024]
    const float* cb = (const float*)d_in[1];   // [128, 256, 8]

    float* cw_embed = (float*)d_out;                               // [4096, 1024]
    float* one_hot  = (float*)d_out + (size_t)BATCH * CWDIM;       // [4096, 128, 256]

    dim3 grid(BATCH / ROWS_PB, CODES);                             // (8, 128)
    vq_fused_kernel<<<grid, THREADS>>>(x, cb, cw_embed, one_hot);
}